// round 3
// baseline (speedup 1.0000x reference)
#include <cuda_runtime.h>
#include <cstdint>

// Problem constants
#define NCH    24          // B*C = 8*3 channels
#define CHPX   (1 << 20)   // pixels per channel (1024*1024)
#define NBINS  256
#define HBLKX  16          // x-blocks per unit in hist kernel
#define HTHR   512         // threads per hist block
#define UNITS  36          // 24 dst units + 12 used-ref units

// Scratch (static device globals — no allocation allowed)
__device__ unsigned int g_hist[2 * NCH * NBINS];     // [0..23]=dst, [24..47]=ref
__device__ float        g_table[NCH * NBINS];        // table value already /255
__device__ unsigned char g_pix[(size_t)NCH * CHPX];  // cached per-pixel LUT index

// Bug-faithful: reference reads table[b*c]; only these k are ever used.
__host__ __device__ __forceinline__ bool chan_used(int k) {
    return (k <= 8) || (k <= 14 && (k & 1) == 0);
}

// ---------------------------------------------------------------------------
// K0: zero the global histograms (required every graph replay)
// ---------------------------------------------------------------------------
__global__ void k_zero_hist() {
    int i = blockIdx.x * blockDim.x + threadIdx.x;
    if (i < 2 * NCH * NBINS) g_hist[i] = 0u;
}

// ---------------------------------------------------------------------------
// K1: pair-histogram. Each unit = one channel-histogram job (or pix-only job).
//   units 0..23  : dst channel k=u   (pix always; hist iff chan_used(k))
//   units 24..35 : ref used channels (hist only)
// Pairs of pixels increment a 256x256 byte-counter joint table (1 smem atomic
// per 2 pixels). 1-D histogram = row sums + column sums.
// Byte counters cannot overflow: 32K pairs/block over 64K pair-bins.
// ---------------------------------------------------------------------------
__constant__ int c_ref_used[12] = {0,1,2,3,4,5,6,7,8,10,12,14};

extern __shared__ unsigned char s_raw[];  // 64KB table + 1KB row-sum stage

__global__ __launch_bounds__(HTHR) void k_hist(const float* __restrict__ dst,
                                               const float* __restrict__ ref) {
    unsigned int* T32   = reinterpret_cast<unsigned int*>(s_raw);          // 16384 words
    unsigned int* stage = reinterpret_cast<unsigned int*>(s_raw + 65536);  // 256 words

    const int u = blockIdx.y;
    const bool is_dst = u < NCH;
    const int k = is_dst ? u : c_ref_used[u - NCH];
    const bool need_hist = is_dst ? chan_used(k) : true;
    const int hist_slot = is_dst ? k : NCH + k;

    const int tid = threadIdx.x;

    if (need_hist) {
        #pragma unroll
        for (int j = tid; j < 16384; j += HTHR) T32[j] = 0u;
        __syncthreads();
    }

    const float* __restrict__ src =
        (is_dst ? dst : ref) + (size_t)k * CHPX;
    const float4* __restrict__ s4 = reinterpret_cast<const float4*>(src);
    uchar4* __restrict__ p4 =
        is_dst ? reinterpret_cast<uchar4*>(g_pix) + (size_t)k * (CHPX / 4)
               : nullptr;

    const float scale = 256.0f / 255.0f;  // f32(BINS/255.0)
    const int n4 = CHPX / 4;
    const int stride = HBLKX * HTHR;

    for (int i = blockIdx.x * HTHR + tid; i < n4; i += stride) {
        float4 v = s4[i];
        // img255 first (f32), then *scale (f32) — bit-faithful to reference
        float t0 = v.x * 255.0f, t1 = v.y * 255.0f;
        float t2 = v.z * 255.0f, t3 = v.w * 255.0f;
        if (need_hist) {
            int i0 = min(max((int)(t0 * scale), 0), 255);
            int i1 = min(max((int)(t1 * scale), 0), 255);
            int i2 = min(max((int)(t2 * scale), 0), 255);
            int i3 = min(max((int)(t3 * scale), 0), 255);
            int idx01 = i0 * 256 + i1;         // pixel0 -> row, pixel1 -> col
            int idx23 = i2 * 256 + i3;
            atomicAdd(&T32[idx01 >> 2], 1u << (8 * (idx01 & 3)));
            atomicAdd(&T32[idx23 >> 2], 1u << (8 * (idx23 & 3)));
        }
        if (is_dst) {
            // pix = clip(trunc(x*255), 0, 255)
            uchar4 p;
            p.x = (unsigned char)min(max((int)t0, 0), 255);
            p.y = (unsigned char)min(max((int)t1, 0), 255);
            p.z = (unsigned char)min(max((int)t2, 0), 255);
            p.w = (unsigned char)min(max((int)t3, 0), 255);
            p4[i] = p;
        }
    }

    if (need_hist) {
        __syncthreads();
        unsigned int cs = 0;
        if (tid < 256) {
            // column sum for bin c = tid: count of second-pixels-of-pair
            const int c = tid;
            const int word = c >> 2, sh = 8 * (c & 3);
            #pragma unroll 8
            for (int i = 0; i < 256; i++) {
                cs += (T32[i * 64 + word] >> sh) & 0xFFu;
            }
        } else {
            // row sum for bin b0 = tid-256 via dp4a over 64 packed words
            const int b0 = tid - 256;
            unsigned int rs = 0;
            #pragma unroll 16
            for (int j = 0; j < 64; j++)
                rs = __dp4a(T32[b0 * 64 + j], 0x01010101u, rs);
            stage[b0] = rs;
        }
        __syncthreads();
        if (tid < 256)
            atomicAdd(&g_hist[hist_slot * NBINS + tid], cs + stage[tid]);
    }
}

// ---------------------------------------------------------------------------
// K2: per-channel CDFs + transfer table (used channels only).
// ---------------------------------------------------------------------------
__global__ void k_table() {
    const int k = blockIdx.x;
    if (!chan_used(k)) return;
    __shared__ float cd[NBINS];
    __shared__ float cr[NBINS];
    const int t = threadIdx.x;  // 256 threads

    // counts sum to exactly 2^20 -> normalization is an exact pow2 multiply
    cd[t] = (float)g_hist[k * NBINS + t] * (1.0f / 1048576.0f);
    cr[t] = (float)g_hist[(NCH + k) * NBINS + t] * (1.0f / 1048576.0f);
    __syncthreads();

    if (t == 0) {  // sequential f32 cumsum, same order as reference
        float a = 0.0f, b = 0.0f;
        for (int i = 0; i < NBINS; i++) {
            a += cd[i]; cd[i] = a;
            b += cr[i]; cr[i] = b;
        }
    }
    __syncthreads();

    int val = t;
    if (t > 0 && t < NBINS - 1) {
        const float x = cd[t];
        #pragma unroll 8
        for (int j = 1; j < NBINS; j++) {
            if (cr[j - 1] <= x && x <= cr[j]) { val = j; break; }
        }
    }
    g_table[k * NBINS + t] = (float)val / 255.0f;
}

// ---------------------------------------------------------------------------
// K3: gather with 32-way bank-replicated LUT (conflict-free LDS).
// Bug-faithful mapping: channel (b,c) uses table[b*c].
// ---------------------------------------------------------------------------
__global__ __launch_bounds__(256) void k_gather(float* __restrict__ out) {
    const int ch = blockIdx.y;          // 0..23 (flat b*3+c)
    const int b = ch / 3, c = ch % 3;
    const int k = b * c;                // bug-faithful table index

    __shared__ float lutR[NBINS * 32];  // lutR[bin*32 + lane]
    const int lane = threadIdx.x & 31;

    // lane-major fill: consecutive threads -> consecutive addresses (no conflicts)
    for (int j = threadIdx.x; j < NBINS * 32; j += blockDim.x)
        lutR[j] = g_table[k * NBINS + (j >> 5)];
    __syncthreads();

    const uchar4* __restrict__ p4 =
        reinterpret_cast<const uchar4*>(g_pix) + (size_t)ch * (CHPX / 4);
    float4* __restrict__ o4 =
        reinterpret_cast<float4*>(out) + (size_t)ch * (CHPX / 4);

    const int n4 = CHPX / 4;
    const int stride = gridDim.x * blockDim.x;
    for (int i = blockIdx.x * blockDim.x + threadIdx.x; i < n4; i += stride) {
        uchar4 p = p4[i];
        o4[i] = make_float4(lutR[p.x * 32 + lane], lutR[p.y * 32 + lane],
                            lutR[p.z * 32 + lane], lutR[p.w * 32 + lane]);
    }
}

// ---------------------------------------------------------------------------
extern "C" void kernel_launch(void* const* d_in, const int* in_sizes, int n_in,
                              void* d_out, int out_size) {
    const float* dst = (const float*)d_in[0];
    const float* ref = (const float*)d_in[1];
    float* out = (float*)d_out;

    static const int HSMEM = 65536 + 1024;
    // Idempotent attribute set (not a stream op; safe under graph capture)
    cudaFuncSetAttribute(k_hist, cudaFuncAttributeMaxDynamicSharedMemorySize,
                         HSMEM);

    k_zero_hist<<<(2 * NCH * NBINS + 255) / 256, 256>>>();
    k_hist<<<dim3(HBLKX, UNITS), HTHR, HSMEM>>>(dst, ref);
    k_table<<<NCH, NBINS>>>();
    k_gather<<<dim3(32, NCH), 256>>>(out);
}

// round 5
// speedup vs baseline: 1.2964x; 1.2964x over previous
#include <cuda_runtime.h>
#include <cstdint>

// Problem constants
#define NCH    24          // B*C = 8*3 channels
#define CHPX   (1 << 20)   // pixels per channel (1024*1024)
#define NBINS  256
#define NWARP  8           // warps per hist block (256 threads)

// Scratch (static device globals — no allocation allowed)
__device__ unsigned int g_hist[2 * NCH * NBINS];     // [0..23]=dst, [24..47]=ref
__device__ float        g_table[NCH * NBINS];        // table value already /255
__device__ unsigned char g_pix[(size_t)NCH * CHPX];  // pix cache (used ch only)

// Bug-faithful: reference reads table[b*c]; only these k are ever used.
__host__ __device__ __forceinline__ bool chan_used(int k) {
    return (k <= 8) || (k <= 14 && (k & 1) == 0);
}

__constant__ unsigned char c_used[12]   = {0,1,2,3,4,5,6,7,8,10,12,14};
__constant__ unsigned char c_unused[12] = {9,11,13,15,16,17,18,19,20,21,22,23};

// ---------------------------------------------------------------------------
// K0: zero the global histograms (required every graph replay)
// ---------------------------------------------------------------------------
__global__ void k_zero_hist() {
    int i = blockIdx.x * blockDim.x + threadIdx.x;
    if (i < 2 * NCH * NBINS) g_hist[i] = 0u;
}

// ---------------------------------------------------------------------------
// K1: histograms for the 24 channel-jobs that actually matter.
//   blockIdx.y in [0,12): dst used channel  (hist + pix-byte write)
//   blockIdx.y in [12,24): ref used channel (hist only)
// Per-warp privatized smem sub-histograms.
// ---------------------------------------------------------------------------
__global__ __launch_bounds__(256) void k_hist(const float* __restrict__ dst,
                                              const float* __restrict__ ref) {
    const int u = blockIdx.y;
    const bool is_dst = u < 12;
    const int k = is_dst ? c_used[u] : c_used[u - 12];
    const int hist_slot = is_dst ? k : NCH + k;

    __shared__ unsigned int sh[NWARP][NBINS];

    const int tid = threadIdx.x;
    const int wid = tid >> 5;

    #pragma unroll
    for (int w = 0; w < NWARP; w++)
        for (int i = tid; i < NBINS; i += blockDim.x) sh[w][i] = 0u;
    __syncthreads();

    const float* __restrict__ src = (is_dst ? dst : ref) + (size_t)k * CHPX;
    const float4* __restrict__ s4 = reinterpret_cast<const float4*>(src);
    uchar4* __restrict__ p4 =
        is_dst ? reinterpret_cast<uchar4*>(g_pix) + (size_t)k * (CHPX / 4)
               : nullptr;

    const float scale = 256.0f / 255.0f;  // f32(BINS/255.0)
    const int n4 = CHPX / 4;
    const int stride = gridDim.x * blockDim.x;

    unsigned int* __restrict__ myh = sh[wid];

    for (int i = blockIdx.x * blockDim.x + tid; i < n4; i += stride) {
        float4 v = __ldcs(&s4[i]);     // streaming: no reuse of raw floats
        // img255 first (f32), then *scale (f32) — bit-faithful to reference
        float t0 = v.x * 255.0f, t1 = v.y * 255.0f;
        float t2 = v.z * 255.0f, t3 = v.w * 255.0f;
        int i0 = min(max((int)(t0 * scale), 0), 255);
        int i1 = min(max((int)(t1 * scale), 0), 255);
        int i2 = min(max((int)(t2 * scale), 0), 255);
        int i3 = min(max((int)(t3 * scale), 0), 255);
        atomicAdd(&myh[i0], 1u);
        atomicAdd(&myh[i1], 1u);
        atomicAdd(&myh[i2], 1u);
        atomicAdd(&myh[i3], 1u);
        if (is_dst) {
            // pix = clip(trunc(x*255), 0, 255); stays L2-resident for gather
            uchar4 p;
            p.x = (unsigned char)min(max((int)t0, 0), 255);
            p.y = (unsigned char)min(max((int)t1, 0), 255);
            p.z = (unsigned char)min(max((int)t2, 0), 255);
            p.w = (unsigned char)min(max((int)t3, 0), 255);
            p4[i] = p;
        }
    }

    __syncthreads();
    for (int i = tid; i < NBINS; i += blockDim.x) {
        unsigned int c = 0;
        #pragma unroll
        for (int w = 0; w < NWARP; w++) c += sh[w][i];
        if (c) atomicAdd(&g_hist[hist_slot * NBINS + i], c);
    }
}

// ---------------------------------------------------------------------------
// K2: per-channel CDFs + transfer table (used channels only).
// ---------------------------------------------------------------------------
__global__ void k_table() {
    const int k = blockIdx.x;
    if (!chan_used(k)) return;
    __shared__ float cd[NBINS];
    __shared__ float cr[NBINS];
    const int t = threadIdx.x;  // 256 threads

    // counts sum to exactly 2^20 -> normalization is an exact pow2 multiply
    cd[t] = (float)g_hist[k * NBINS + t] * (1.0f / 1048576.0f);
    cr[t] = (float)g_hist[(NCH + k) * NBINS + t] * (1.0f / 1048576.0f);
    __syncthreads();

    if (t == 0) {  // sequential f32 cumsum, same order as reference
        float a = 0.0f, b = 0.0f;
        for (int i = 0; i < NBINS; i++) {
            a += cd[i]; cd[i] = a;
            b += cr[i]; cr[i] = b;
        }
    }
    __syncthreads();

    int val = t;
    if (t > 0 && t < NBINS - 1) {
        const float x = cd[t];
        #pragma unroll 8
        for (int j = 1; j < NBINS; j++) {
            if (cr[j - 1] <= x && x <= cr[j]) { val = j; break; }
        }
    }
    g_table[k * NBINS + t] = (float)val / 255.0f;
}

// ---------------------------------------------------------------------------
// K3: gather. Bug-faithful mapping: channel (b,c) uses table[b*c].
//   blockIdx.y in [0,12):  used dst channel   -> read cached pix bytes
//   blockIdx.y in [12,24): unused dst channel -> read fp32, index inline
// ---------------------------------------------------------------------------
__global__ __launch_bounds__(256) void k_gather(const float* __restrict__ dst,
                                                float* __restrict__ out) {
    const int u = blockIdx.y;
    const bool from_pix = u < 12;
    const int ch = from_pix ? c_used[u] : c_unused[u - 12];
    const int b = ch / 3, c = ch % 3;
    const int k = b * c;                // bug-faithful table index

    __shared__ float lut[NBINS];
    if (threadIdx.x < NBINS) lut[threadIdx.x] = g_table[k * NBINS + threadIdx.x];
    __syncthreads();

    float4* __restrict__ o4 =
        reinterpret_cast<float4*>(out) + (size_t)ch * (CHPX / 4);
    const int n4 = CHPX / 4;
    const int stride = gridDim.x * blockDim.x;

    if (from_pix) {
        const uchar4* __restrict__ p4 =
            reinterpret_cast<const uchar4*>(g_pix) + (size_t)ch * (CHPX / 4);
        for (int i = blockIdx.x * blockDim.x + threadIdx.x; i < n4; i += stride) {
            uchar4 p = p4[i];
            o4[i] = make_float4(lut[p.x], lut[p.y], lut[p.z], lut[p.w]);
        }
    } else {
        const float4* __restrict__ s4 =
            reinterpret_cast<const float4*>(dst) + (size_t)ch * (CHPX / 4);
        for (int i = blockIdx.x * blockDim.x + threadIdx.x; i < n4; i += stride) {
            float4 v = __ldcs(&s4[i]);
            int i0 = min(max((int)(v.x * 255.0f), 0), 255);
            int i1 = min(max((int)(v.y * 255.0f), 0), 255);
            int i2 = min(max((int)(v.z * 255.0f), 0), 255);
            int i3 = min(max((int)(v.w * 255.0f), 0), 255);
            o4[i] = make_float4(lut[i0], lut[i1], lut[i2], lut[i3]);
        }
    }
}

// ---------------------------------------------------------------------------
extern "C" void kernel_launch(void* const* d_in, const int* in_sizes, int n_in,
                              void* d_out, int out_size) {
    const float* dst = (const float*)d_in[0];
    const float* ref = (const float*)d_in[1];
    float* out = (float*)d_out;

    k_zero_hist<<<(2 * NCH * NBINS + 255) / 256, 256>>>();
    k_hist<<<dim3(64, 24), 256>>>(dst, ref);
    k_table<<<NCH, NBINS>>>();
    k_gather<<<dim3(64, 24), 256>>>(dst, out);
}